// round 16
// baseline (speedup 1.0000x reference)
#include <cuda_runtime.h>
#include <cuda_fp16.h>
#include <cstdint>

#define SEQ 2048
#define EMB 1024
#define HEADS 16
#define BATCH 2
#define HD 64
#define NSPLIT 4

__device__ __half g_q[(size_t)BATCH * HEADS * SEQ * HD];
__device__ __half g_k[(size_t)BATCH * HEADS * SEQ * HD];
__device__ __half g_v[(size_t)BATCH * HEADS * SEQ * HD];
__device__ __half g_xh[(size_t)BATCH * SEQ * EMB];
__device__ __half g_wh[(size_t)3 * EMB * EMB];
__device__ __half g_po[(size_t)NSPLIT * BATCH * HEADS * SEQ * HD];
__device__ float  g_pl[(size_t)NSPLIT * BATCH * HEADS * SEQ];

__device__ __forceinline__ uint32_t smem_u32(const void* p) {
    uint32_t a;
    asm("{ .reg .u64 t; cvta.to.shared.u64 t, %1; cvt.u32.u64 %0, t; }"
        : "=r"(a) : "l"(p));
    return a;
}
__device__ __forceinline__ uint32_t h2u(__half2 h) { return *(uint32_t*)&h; }
__device__ __forceinline__ uint32_t ex2h2(uint32_t x) {
    uint32_t r;
    asm("ex2.approx.f16x2 %0, %1;" : "=r"(r) : "r"(x));
    return r;
}
__device__ __forceinline__ void ldsm4(uint32_t& r0, uint32_t& r1, uint32_t& r2,
                                      uint32_t& r3, uint32_t addr) {
    asm volatile("ldmatrix.sync.aligned.m8n8.x4.shared.b16 {%0,%1,%2,%3}, [%4];"
                 : "=r"(r0), "=r"(r1), "=r"(r2), "=r"(r3) : "r"(addr));
}
__device__ __forceinline__ void ldsm4t(uint32_t& r0, uint32_t& r1, uint32_t& r2,
                                       uint32_t& r3, uint32_t addr) {
    asm volatile("ldmatrix.sync.aligned.m8n8.x4.trans.shared.b16 {%0,%1,%2,%3}, [%4];"
                 : "=r"(r0), "=r"(r1), "=r"(r2), "=r"(r3) : "r"(addr));
}
__device__ __forceinline__ void mma16(float* d, const uint32_t* a, uint32_t b0, uint32_t b1) {
    asm volatile(
        "mma.sync.aligned.m16n8k16.row.col.f32.f16.f16.f32 "
        "{%0,%1,%2,%3}, {%4,%5,%6,%7}, {%8,%9}, {%0,%1,%2,%3};"
        : "+f"(d[0]), "+f"(d[1]), "+f"(d[2]), "+f"(d[3])
        : "r"(a[0]), "r"(a[1]), "r"(a[2]), "r"(a[3]), "r"(b0), "r"(b1));
}
__device__ __forceinline__ void mma16h(uint32_t* d, const uint32_t* a, uint32_t b0, uint32_t b1) {
    asm volatile(
        "mma.sync.aligned.m16n8k16.row.col.f16.f16.f16.f16 "
        "{%0,%1}, {%2,%3,%4,%5}, {%6,%7}, {%0,%1};"
        : "+r"(d[0]), "+r"(d[1])
        : "r"(a[0]), "r"(a[1]), "r"(a[2]), "r"(a[3]), "r"(b0), "r"(b1));
}
#define CP16(dst, src) \
    asm volatile("cp.async.cg.shared.global [%0], [%1], 16;" :: "r"(dst), "l"(src))
#define CP_COMMIT() asm volatile("cp.async.commit_group;" ::: "memory")
#define CP_WAIT(n)  asm volatile("cp.async.wait_group %0;" :: "n"(n) : "memory")

#define EXPC 0.04508422012779510f

// ---------------------------------------------------------------------------
// fp32 -> fp16 convert for X and W in one launch.
// ---------------------------------------------------------------------------
__global__ void __launch_bounds__(256)
cvt_h(const float* __restrict__ x, const float* __restrict__ w,
      __half* __restrict__ xh, __half* __restrict__ wh, int n4x, int n4tot)
{
    for (int i = blockIdx.x * blockDim.x + threadIdx.x; i < n4tot;
         i += gridDim.x * blockDim.x) {
        const float* s;
        __half* d;
        int j;
        if (i < n4x) { s = x; d = xh; j = i; }
        else         { s = w; d = wh; j = i - n4x; }
        float4 v = ((const float4*)s)[j];
        uint2 o;
        o.x = h2u(__floats2half2_rn(v.x, v.y));
        o.y = h2u(__floats2half2_rn(v.z, v.w));
        ((uint2*)d)[j] = o;
    }
}

// ---------------------------------------------------------------------------
// QKV GEMM: 256 thr, CTA tile 128x128, 8 warps of 64x32 (2 m-warps x 4
// n-warps), kc=64, 3 stages x 32KB = 96KB -> 2 CTAs/SM = 4 warps/SMSP.
// ---------------------------------------------------------------------------
#define G_STAGE 32768
#define G_SMEM  98304

__global__ void __launch_bounds__(256, 2)
qkv_h(const float* __restrict__ bias)
{
    extern __shared__ char sm[];
    const uint32_t sb = smem_u32(sm);
    const int tid = threadIdx.x;
    const int lane = tid & 31, wid = tid >> 5;
    const int qd = lane & 3;
    const int wm = wid & 1, wn = wid >> 1;          // wn in 0..3
    const int m0 = blockIdx.y * 128, n0 = blockIdx.x * 128;

    const char* Xb = (const char*)g_xh + (size_t)m0 * EMB * 2;
    const char* Wb = (const char*)g_wh + (size_t)n0 * EMB * 2;
    // loader: 1024 chunks per operand per stage; 4 A + 4 B per thread.
    uint32_t so[4], go[4];
#pragma unroll
    for (int i = 0; i < 4; i++) {
        int cid = tid + i * 256;
        int row = cid >> 3, c = cid & 7;
        so[i] = (uint32_t)(row * 8 + (c ^ (row & 7))) * 16;
        go[i] = (uint32_t)(row * (EMB * 2) + c * 16);
    }

    const int rowm = (lane & 7) + 8 * ((lane >> 3) & 1);
    const int ca = lane >> 4;
    int ra[4], rb[2];
#pragma unroll
    for (int mt = 0; mt < 4; mt++) ra[mt] = wm * 64 + mt * 16 + rowm;
#pragma unroll
    for (int g = 0; g < 2; g++) rb[g] = wn * 32 + g * 16 + rowm;

    float acc[4][4][4];
#pragma unroll
    for (int mt = 0; mt < 4; mt++)
#pragma unroll
        for (int nt = 0; nt < 4; nt++)
#pragma unroll
            for (int e = 0; e < 4; e++) acc[mt][nt][e] = 0.f;

#pragma unroll
    for (int p = 0; p < 2; p++) {
        const uint32_t Ab = sb + p * G_STAGE;
#pragma unroll
        for (int i = 0; i < 4; i++) {
            CP16(Ab + so[i], Xb + go[i] + p * 128);
            CP16(Ab + 16384 + so[i], Wb + go[i] + p * 128);
        }
        CP_COMMIT();
    }

    for (int kt = 0; kt < 16; kt++) {
        const int s = kt - (kt / 3) * 3;
        CP_WAIT(1);
        __syncthreads();
        if (kt + 2 < 16) {
            const int s2 = (kt + 2) - ((kt + 2) / 3) * 3;
            const uint32_t Ab2 = sb + s2 * G_STAGE;
            const uint32_t kofs = (uint32_t)(kt + 2) * 128;
#pragma unroll
            for (int i = 0; i < 4; i++) {
                CP16(Ab2 + so[i], Xb + go[i] + kofs);
                CP16(Ab2 + 16384 + so[i], Wb + go[i] + kofs);
            }
        }
        CP_COMMIT();

        const uint32_t Ab = sb + s * G_STAGE;
        const uint32_t Bb = Ab + 16384;
#pragma unroll
        for (int ks = 0; ks < 4; ks++) {
            const int c = ks * 2 + ca;
            uint32_t aF[4][4];
#pragma unroll
            for (int mt = 0; mt < 4; mt++)
                ldsm4(aF[mt][0], aF[mt][1], aF[mt][2], aF[mt][3],
                      Ab + (uint32_t)(ra[mt] * 8 + (c ^ (ra[mt] & 7))) * 16);
#pragma unroll
            for (int g = 0; g < 2; g++) {
                uint32_t r0, r1, r2, r3;
                ldsm4(r0, r1, r2, r3,
                      Bb + (uint32_t)(rb[g] * 8 + (c ^ (rb[g] & 7))) * 16);
#pragma unroll
                for (int mt = 0; mt < 4; mt++) {
                    mma16(acc[mt][2 * g], aF[mt], r0, r2);
                    mma16(acc[mt][2 * g + 1], aF[mt], r1, r3);
                }
            }
        }
    }

    const int which = n0 >> 10;
    __half* dst = (which == 0) ? g_q : (which == 1) ? g_k : g_v;
    const float sc = (which == 0) ? EXPC : 1.0f;
#pragma unroll
    for (int nt = 0; nt < 4; nt++) {
        const int f = n0 + wn * 32 + nt * 8 + 2 * qd;
        const float b0 = bias[f], b1 = bias[f + 1];
        const int e = f & (EMB - 1);
        const int h = e >> 6, d = e & 63;
#pragma unroll
        for (int mt = 0; mt < 4; mt++) {
            const int m = m0 + wm * 64 + mt * 16 + (lane >> 2);
            const int bb = m >> 11, n = m & (SEQ - 1);
            __half* p = dst + ((size_t)((bb * HEADS + h) * SEQ + n)) * HD + d;
            *(__half2*)p = __floats2half2_rn((acc[mt][nt][0] + b0) * sc,
                                             (acc[mt][nt][1] + b1) * sc);
            *(__half2*)(p + (size_t)8 * HD) =
                __floats2half2_rn((acc[mt][nt][2] + b0) * sc,
                                  (acc[mt][nt][3] + b1) * sc);
        }
    }
}

// ---------------------------------------------------------------------------
// Flash attention (R14 version, unchanged): split-KV x4, fp16 S-accumulators,
// ex2.f16x2 in place, row sums via ones-mma, 3-stage pipeline.
// ---------------------------------------------------------------------------
#define A_SMEM 65536
#define ONES_H2 0x3C003C00u

__global__ void __launch_bounds__(128, 3)
attn_h()
{
    extern __shared__ char sm[];
    const uint32_t sb = smem_u32(sm);
    const int tid = threadIdx.x;
    const int lane = tid & 31, w = tid >> 5;
    const int qd = lane & 3;
    const int bh = blockIdx.y;
    const int q0 = blockIdx.x * 128;
    const int z = blockIdx.z;

    const char* Qg = (const char*)g_q + ((size_t)bh * SEQ * HD + (size_t)q0 * HD) * 2;
    const char* Kg = (const char*)g_k + (size_t)bh * SEQ * HD * 2 + (size_t)z * 65536;
    const char* Vg = (const char*)g_v + (size_t)bh * SEQ * HD * 2 + (size_t)z * 65536;

    uint32_t lso[4];
    ptrdiff_t lgo[4];
#pragma unroll
    for (int i = 0; i < 4; i++) {
        int cid = tid + i * 128;
        int row = cid >> 3, c = cid & 7;
        lso[i] = (uint32_t)(row * 8 + (c ^ (row & 7))) * 16;
        lgo[i] = cid * 16;
    }

#pragma unroll
    for (int i = 0; i < 8; i++) {
        int cid = tid + i * 128;
        int row = cid >> 3, c = cid & 7;
        CP16(sb + (uint32_t)(row * 8 + (c ^ (row & 7))) * 16, Qg + cid * 16);
    }
    CP_COMMIT();
#pragma unroll
    for (int p = 0; p < 2; p++) {
        const uint32_t stb = sb + 16384 + p * 16384;
#pragma unroll
        for (int i = 0; i < 4; i++) {
            CP16(stb + lso[i], Kg + (size_t)p * 8192 + lgo[i]);
            CP16(stb + 8192 + lso[i], Vg + (size_t)p * 8192 + lgo[i]);
        }
        CP_COMMIT();
    }

    CP_WAIT(2);
    __syncthreads();
    const int rowm = (lane & 7) + 8 * ((lane >> 3) & 1);
    const int ca = lane >> 4;
    uint32_t aQ[2][4][4];
#pragma unroll
    for (int h = 0; h < 2; h++) {
        const int rq = w * 32 + h * 16 + rowm;
        const uint32_t rq8 = rq * 8, rqx = rq & 7;
#pragma unroll
        for (int ks = 0; ks < 4; ks++) {
            const uint32_t c = ks * 2 + ca;
            ldsm4(aQ[h][ks][0], aQ[h][ks][1], aQ[h][ks][2], aQ[h][ks][3],
                  sb + (rq8 + (c ^ rqx)) * 16);
        }
    }
    uint32_t r8[4], rx[4];
#pragma unroll
    for (int g = 0; g < 4; g++) {
        int r = g * 16 + rowm;
        r8[g] = (uint32_t)r * 8;
        rx[g] = (uint32_t)(r & 7);
    }

    float oacc[2][8][4];
#pragma unroll
    for (int h = 0; h < 2; h++)
#pragma unroll
        for (int i = 0; i < 8; i++)
#pragma unroll
            for (int e = 0; e < 4; e++) oacc[h][i][e] = 0.f;
    float rsacc[2][4];
#pragma unroll
    for (int h = 0; h < 2; h++)
#pragma unroll
        for (int e = 0; e < 4; e++) rsacc[h][e] = 0.f;

    for (int t = 0; t < 8; t++) {
        const int s = t - (t / 3) * 3;
        CP_WAIT(1);
        __syncthreads();
        if (t + 2 < 8) {
            const int s2 = (t + 2) - ((t + 2) / 3) * 3;
            const uint32_t stb = sb + 16384 + s2 * 16384;
            const ptrdiff_t ko = (ptrdiff_t)(t + 2) * 8192;
#pragma unroll
            for (int i = 0; i < 4; i++) {
                CP16(stb + lso[i], Kg + ko + lgo[i]);
                CP16(stb + 8192 + lso[i], Vg + ko + lgo[i]);
            }
        }
        CP_COMMIT();

        const uint32_t Kst = sb + 16384 + s * 16384;
        const uint32_t Vst = Kst + 8192;

        uint32_t sacc[2][8][2];
#pragma unroll
        for (int h = 0; h < 2; h++)
#pragma unroll
            for (int nt = 0; nt < 8; nt++) {
                sacc[h][nt][0] = 0u;
                sacc[h][nt][1] = 0u;
            }
#pragma unroll
        for (int g = 0; g < 4; g++) {
#pragma unroll
            for (int ks = 0; ks < 4; ks++) {
                const uint32_t c = ks * 2 + ca;
                uint32_t r0, r1, r2, r3;
                ldsm4(r0, r1, r2, r3, Kst + (r8[g] + (c ^ rx[g])) * 16);
                mma16h(sacc[0][2 * g], aQ[0][ks], r0, r2);
                mma16h(sacc[0][2 * g + 1], aQ[0][ks], r1, r3);
                mma16h(sacc[1][2 * g], aQ[1][ks], r0, r2);
                mma16h(sacc[1][2 * g + 1], aQ[1][ks], r1, r3);
            }
        }

#pragma unroll
        for (int h = 0; h < 2; h++)
#pragma unroll
            for (int nt = 0; nt < 8; nt++) {
                sacc[h][nt][0] = ex2h2(sacc[h][nt][0]);
                sacc[h][nt][1] = ex2h2(sacc[h][nt][1]);
            }

#pragma unroll
        for (int jj = 0; jj < 4; jj++) {
            uint32_t aP0[4] = {sacc[0][2 * jj][0], sacc[0][2 * jj][1],
                               sacc[0][2 * jj + 1][0], sacc[0][2 * jj + 1][1]};
            uint32_t aP1[4] = {sacc[1][2 * jj][0], sacc[1][2 * jj][1],
                               sacc[1][2 * jj + 1][0], sacc[1][2 * jj + 1][1]};
#pragma unroll
            for (int g4 = 0; g4 < 4; g4++) {
                const uint32_t c = g4 * 2 + ca;
                uint32_t v0, v1, v2, v3;
                ldsm4t(v0, v1, v2, v3, Vst + (r8[jj] + (c ^ rx[jj])) * 16);
                mma16(oacc[0][2 * g4], aP0, v0, v1);
                mma16(oacc[0][2 * g4 + 1], aP0, v2, v3);
                mma16(oacc[1][2 * g4], aP1, v0, v1);
                mma16(oacc[1][2 * g4 + 1], aP1, v2, v3);
            }
            mma16(rsacc[0], aP0, ONES_H2, ONES_H2);
            mma16(rsacc[1], aP1, ONES_H2, ONES_H2);
        }
    }

#pragma unroll
    for (int h = 0; h < 2; h++) {
        const int qrow = q0 + w * 32 + h * 16 + (lane >> 2);
        __half* po0 = g_po + (((size_t)(z * BATCH * HEADS + bh)) * SEQ + qrow) * HD + 2 * qd;
        __half* po1 = po0 + (size_t)8 * HD;
#pragma unroll
        for (int od = 0; od < 8; od++) {
            *(__half2*)(po0 + od * 8) = __floats2half2_rn(oacc[h][od][0], oacc[h][od][1]);
            *(__half2*)(po1 + od * 8) = __floats2half2_rn(oacc[h][od][2], oacc[h][od][3]);
        }
        if (qd == 0) {
            float* pl = g_pl + ((size_t)(z * BATCH * HEADS + bh)) * SEQ + qrow;
            pl[0] = rsacc[h][0];
            pl[8] = rsacc[h][2];
        }
    }
}

// ---------------------------------------------------------------------------
// Merge + normalize.
// ---------------------------------------------------------------------------
__global__ void __launch_bounds__(256)
merge_h(float* __restrict__ out)
{
    const int idx = blockIdx.x * blockDim.x + threadIdx.x;
    const int dc = idx & 7;
    const int q = (idx >> 3) & (SEQ - 1);
    const int bh = idx >> 14;

    float acc[8];
#pragma unroll
    for (int i = 0; i < 8; i++) acc[i] = 0.f;
    float l = 0.f;

#pragma unroll
    for (int z = 0; z < NSPLIT; z++) {
        const size_t base = ((size_t)(z * BATCH * HEADS + bh)) * SEQ + q;
        uint4 u = *(const uint4*)(g_po + base * HD + dc * 8);
        float2 f;
        f = __half22float2(*(__half2*)&u.x); acc[0] += f.x; acc[1] += f.y;
        f = __half22float2(*(__half2*)&u.y); acc[2] += f.x; acc[3] += f.y;
        f = __half22float2(*(__half2*)&u.z); acc[4] += f.x; acc[5] += f.y;
        f = __half22float2(*(__half2*)&u.w); acc[6] += f.x; acc[7] += f.y;
        l += g_pl[base];
    }
    const float inv = 1.f / l;
    const int b = bh >> 4, h = bh & 15;
    float* o = out + ((size_t)(b * SEQ + q)) * EMB + h * 64 + dc * 8;
    float4 v;
    v.x = acc[0] * inv; v.y = acc[1] * inv; v.z = acc[2] * inv; v.w = acc[3] * inv;
    *(float4*)o = v;
    v.x = acc[4] * inv; v.y = acc[5] * inv; v.z = acc[6] * inv; v.w = acc[7] * inv;
    *(float4*)(o + 4) = v;
}

extern "C" void kernel_launch(void* const* d_in, const int* in_sizes, int n_in,
                              void* d_out, int out_size)
{
    const float* x = (const float*)d_in[0];
    const float* w = (const float*)d_in[1];
    const float* b = (const float*)d_in[2];
    float* out = (float*)d_out;

    __half* xh;  cudaGetSymbolAddress((void**)&xh, g_xh);
    __half* wh;  cudaGetSymbolAddress((void**)&wh, g_wh);

    cudaFuncSetAttribute(qkv_h, cudaFuncAttributeMaxDynamicSharedMemorySize, G_SMEM);
    cudaFuncSetAttribute(attn_h, cudaFuncAttributeMaxDynamicSharedMemorySize, A_SMEM);

    const int n4x = BATCH * SEQ * EMB / 4;
    const int n4w = 3 * EMB * EMB / 4;
    cvt_h<<<592, 256>>>(x, w, xh, wh, n4x, n4x + n4w);
    qkv_h<<<dim3(3 * EMB / 128, BATCH * SEQ / 128), 256, G_SMEM>>>(b);
    attn_h<<<dim3(SEQ / 128, BATCH * HEADS, NSPLIT), 128, A_SMEM>>>();
    merge_h<<<(BATCH * HEADS * SEQ * HD / 8) / 256, 256>>>(out);
}

// round 17
// speedup vs baseline: 1.0531x; 1.0531x over previous
#include <cuda_runtime.h>
#include <cuda_fp16.h>
#include <cstdint>

#define SEQ 2048
#define EMB 1024
#define HEADS 16
#define BATCH 2
#define HD 64
#define NSPLIT 4

__device__ __half g_q[(size_t)BATCH * HEADS * SEQ * HD];
__device__ __half g_k[(size_t)BATCH * HEADS * SEQ * HD];
__device__ __half g_v[(size_t)BATCH * HEADS * SEQ * HD];
__device__ __half g_xh[(size_t)BATCH * SEQ * EMB];
__device__ __half g_wh[(size_t)3 * EMB * EMB];
__device__ __half g_po[(size_t)NSPLIT * BATCH * HEADS * SEQ * HD];
__device__ float  g_pl[(size_t)NSPLIT * BATCH * HEADS * SEQ];

__device__ __forceinline__ uint32_t smem_u32(const void* p) {
    uint32_t a;
    asm("{ .reg .u64 t; cvta.to.shared.u64 t, %1; cvt.u32.u64 %0, t; }"
        : "=r"(a) : "l"(p));
    return a;
}
__device__ __forceinline__ uint32_t h2u(__half2 h) { return *(uint32_t*)&h; }
__device__ __forceinline__ uint32_t ex2h2(uint32_t x) {
    uint32_t r;
    asm("ex2.approx.f16x2 %0, %1;" : "=r"(r) : "r"(x));
    return r;
}
__device__ __forceinline__ void ldsm4(uint32_t& r0, uint32_t& r1, uint32_t& r2,
                                      uint32_t& r3, uint32_t addr) {
    asm volatile("ldmatrix.sync.aligned.m8n8.x4.shared.b16 {%0,%1,%2,%3}, [%4];"
                 : "=r"(r0), "=r"(r1), "=r"(r2), "=r"(r3) : "r"(addr));
}
__device__ __forceinline__ void ldsm4t(uint32_t& r0, uint32_t& r1, uint32_t& r2,
                                       uint32_t& r3, uint32_t addr) {
    asm volatile("ldmatrix.sync.aligned.m8n8.x4.trans.shared.b16 {%0,%1,%2,%3}, [%4];"
                 : "=r"(r0), "=r"(r1), "=r"(r2), "=r"(r3) : "r"(addr));
}
__device__ __forceinline__ void mma16(float* d, const uint32_t* a, uint32_t b0, uint32_t b1) {
    asm volatile(
        "mma.sync.aligned.m16n8k16.row.col.f32.f16.f16.f32 "
        "{%0,%1,%2,%3}, {%4,%5,%6,%7}, {%8,%9}, {%0,%1,%2,%3};"
        : "+f"(d[0]), "+f"(d[1]), "+f"(d[2]), "+f"(d[3])
        : "r"(a[0]), "r"(a[1]), "r"(a[2]), "r"(a[3]), "r"(b0), "r"(b1));
}
__device__ __forceinline__ void mma16h(uint32_t* d, const uint32_t* a, uint32_t b0, uint32_t b1) {
    asm volatile(
        "mma.sync.aligned.m16n8k16.row.col.f16.f16.f16.f16 "
        "{%0,%1}, {%2,%3,%4,%5}, {%6,%7}, {%0,%1};"
        : "+r"(d[0]), "+r"(d[1])
        : "r"(a[0]), "r"(a[1]), "r"(a[2]), "r"(a[3]), "r"(b0), "r"(b1));
}
#define CP16(dst, src) \
    asm volatile("cp.async.cg.shared.global [%0], [%1], 16;" :: "r"(dst), "l"(src))
#define CP_COMMIT() asm volatile("cp.async.commit_group;" ::: "memory")
#define CP_WAIT(n)  asm volatile("cp.async.wait_group %0;" :: "n"(n) : "memory")

#define EXPC 0.04508422012779510f

// ---------------------------------------------------------------------------
// fp32 -> fp16 convert for X and W in one launch.
// ---------------------------------------------------------------------------
__global__ void __launch_bounds__(256)
cvt_h(const float* __restrict__ x, const float* __restrict__ w,
      __half* __restrict__ xh, __half* __restrict__ wh, int n4x, int n4tot)
{
    for (int i = blockIdx.x * blockDim.x + threadIdx.x; i < n4tot;
         i += gridDim.x * blockDim.x) {
        const float* s;
        __half* d;
        int j;
        if (i < n4x) { s = x; d = xh; j = i; }
        else         { s = w; d = wh; j = i - n4x; }
        float4 v = ((const float4*)s)[j];
        uint2 o;
        o.x = h2u(__floats2half2_rn(v.x, v.y));
        o.y = h2u(__floats2half2_rn(v.z, v.w));
        ((uint2*)d)[j] = o;
    }
}

// ---------------------------------------------------------------------------
// QKV GEMM (R14 config, reverted — best known): CTA tile 128x64, 4 warps of
// 64x32, kc=64, 3 stages x 24KB = 72KB -> 3 CTAs/SM.
// ---------------------------------------------------------------------------
#define G_STAGE 24576
#define G_SMEM  73728

__global__ void __launch_bounds__(128, 3)
qkv_h(const float* __restrict__ bias)
{
    extern __shared__ char sm[];
    const uint32_t sb = smem_u32(sm);
    const int tid = threadIdx.x;
    const int lane = tid & 31, wid = tid >> 5;
    const int qd = lane & 3;
    const int wm = wid & 1, wn = wid >> 1;
    const int m0 = blockIdx.y * 128, n0 = blockIdx.x * 64;

    const char* Xb = (const char*)g_xh + (size_t)m0 * EMB * 2;
    const char* Wb = (const char*)g_wh + (size_t)n0 * EMB * 2;
    uint32_t so[8], go[8];
#pragma unroll
    for (int i = 0; i < 8; i++) {
        int cid = tid + i * 128;
        int row = cid >> 3, c = cid & 7;
        so[i] = (uint32_t)(row * 8 + (c ^ (row & 7))) * 16;
        go[i] = (uint32_t)(row * (EMB * 2) + c * 16);
    }

    const int rowm = (lane & 7) + 8 * ((lane >> 3) & 1);
    const int ca = lane >> 4;
    int ra[4], rb[2];
#pragma unroll
    for (int mt = 0; mt < 4; mt++) ra[mt] = wm * 64 + mt * 16 + rowm;
#pragma unroll
    for (int g = 0; g < 2; g++) rb[g] = wn * 32 + g * 16 + rowm;

    float acc[4][4][4];
#pragma unroll
    for (int mt = 0; mt < 4; mt++)
#pragma unroll
        for (int nt = 0; nt < 4; nt++)
#pragma unroll
            for (int e = 0; e < 4; e++) acc[mt][nt][e] = 0.f;

#pragma unroll
    for (int p = 0; p < 2; p++) {
        const uint32_t Ab = sb + p * G_STAGE;
#pragma unroll
        for (int i = 0; i < 8; i++)
            CP16(Ab + so[i], Xb + go[i] + p * 128);
#pragma unroll
        for (int i = 0; i < 4; i++)
            CP16(Ab + 16384 + so[i], Wb + go[i] + p * 128);
        CP_COMMIT();
    }

    for (int kt = 0; kt < 16; kt++) {
        const int s = kt - (kt / 3) * 3;
        CP_WAIT(1);
        __syncthreads();
        if (kt + 2 < 16) {
            const int s2 = (kt + 2) - ((kt + 2) / 3) * 3;
            const uint32_t Ab2 = sb + s2 * G_STAGE;
            const uint32_t kofs = (uint32_t)(kt + 2) * 128;
#pragma unroll
            for (int i = 0; i < 8; i++)
                CP16(Ab2 + so[i], Xb + go[i] + kofs);
#pragma unroll
            for (int i = 0; i < 4; i++)
                CP16(Ab2 + 16384 + so[i], Wb + go[i] + kofs);
        }
        CP_COMMIT();

        const uint32_t Ab = sb + s * G_STAGE;
        const uint32_t Bb = Ab + 16384;
#pragma unroll
        for (int ks = 0; ks < 4; ks++) {
            const int c = ks * 2 + ca;
            uint32_t aF[4][4];
#pragma unroll
            for (int mt = 0; mt < 4; mt++)
                ldsm4(aF[mt][0], aF[mt][1], aF[mt][2], aF[mt][3],
                      Ab + (uint32_t)(ra[mt] * 8 + (c ^ (ra[mt] & 7))) * 16);
#pragma unroll
            for (int g = 0; g < 2; g++) {
                uint32_t r0, r1, r2, r3;
                ldsm4(r0, r1, r2, r3,
                      Bb + (uint32_t)(rb[g] * 8 + (c ^ (rb[g] & 7))) * 16);
#pragma unroll
                for (int mt = 0; mt < 4; mt++) {
                    mma16(acc[mt][2 * g], aF[mt], r0, r2);
                    mma16(acc[mt][2 * g + 1], aF[mt], r1, r3);
                }
            }
        }
    }

    const int which = n0 >> 10;
    __half* dst = (which == 0) ? g_q : (which == 1) ? g_k : g_v;
    const float sc = (which == 0) ? EXPC : 1.0f;
#pragma unroll
    for (int nt = 0; nt < 4; nt++) {
        const int f = n0 + wn * 32 + nt * 8 + 2 * qd;
        const float b0 = bias[f], b1 = bias[f + 1];
        const int e = f & (EMB - 1);
        const int h = e >> 6, d = e & 63;
#pragma unroll
        for (int mt = 0; mt < 4; mt++) {
            const int m = m0 + wm * 64 + mt * 16 + (lane >> 2);
            const int bb = m >> 11, n = m & (SEQ - 1);
            __half* p = dst + ((size_t)((bb * HEADS + h) * SEQ + n)) * HD + d;
            *(__half2*)p = __floats2half2_rn((acc[mt][nt][0] + b0) * sc,
                                             (acc[mt][nt][1] + b1) * sc);
            *(__half2*)(p + (size_t)8 * HD) =
                __floats2half2_rn((acc[mt][nt][2] + b0) * sc,
                                  (acc[mt][nt][3] + b1) * sc);
        }
    }
}

// ---------------------------------------------------------------------------
// Flash attention (R14 config) with the t-loop FULLY UNROLLED: stage indices
// and addresses become compile-time constants; ptxas can pipeline across the
// per-tile barriers.
// ---------------------------------------------------------------------------
#define A_SMEM 65536
#define ONES_H2 0x3C003C00u

__global__ void __launch_bounds__(128, 3)
attn_h()
{
    extern __shared__ char sm[];
    const uint32_t sb = smem_u32(sm);
    const int tid = threadIdx.x;
    const int lane = tid & 31, w = tid >> 5;
    const int qd = lane & 3;
    const int bh = blockIdx.y;
    const int q0 = blockIdx.x * 128;
    const int z = blockIdx.z;

    const char* Qg = (const char*)g_q + ((size_t)bh * SEQ * HD + (size_t)q0 * HD) * 2;
    const char* Kg = (const char*)g_k + (size_t)bh * SEQ * HD * 2 + (size_t)z * 65536;
    const char* Vg = (const char*)g_v + (size_t)bh * SEQ * HD * 2 + (size_t)z * 65536;

    uint32_t lso[4];
    ptrdiff_t lgo[4];
#pragma unroll
    for (int i = 0; i < 4; i++) {
        int cid = tid + i * 128;
        int row = cid >> 3, c = cid & 7;
        lso[i] = (uint32_t)(row * 8 + (c ^ (row & 7))) * 16;
        lgo[i] = cid * 16;
    }

#pragma unroll
    for (int i = 0; i < 8; i++) {
        int cid = tid + i * 128;
        int row = cid >> 3, c = cid & 7;
        CP16(sb + (uint32_t)(row * 8 + (c ^ (row & 7))) * 16, Qg + cid * 16);
    }
    CP_COMMIT();
#pragma unroll
    for (int p = 0; p < 2; p++) {
        const uint32_t stb = sb + 16384 + p * 16384;
#pragma unroll
        for (int i = 0; i < 4; i++) {
            CP16(stb + lso[i], Kg + (size_t)p * 8192 + lgo[i]);
            CP16(stb + 8192 + lso[i], Vg + (size_t)p * 8192 + lgo[i]);
        }
        CP_COMMIT();
    }

    CP_WAIT(2);
    __syncthreads();
    const int rowm = (lane & 7) + 8 * ((lane >> 3) & 1);
    const int ca = lane >> 4;
    uint32_t aQ[2][4][4];
#pragma unroll
    for (int h = 0; h < 2; h++) {
        const int rq = w * 32 + h * 16 + rowm;
        const uint32_t rq8 = rq * 8, rqx = rq & 7;
#pragma unroll
        for (int ks = 0; ks < 4; ks++) {
            const uint32_t c = ks * 2 + ca;
            ldsm4(aQ[h][ks][0], aQ[h][ks][1], aQ[h][ks][2], aQ[h][ks][3],
                  sb + (rq8 + (c ^ rqx)) * 16);
        }
    }
    uint32_t r8[4], rx[4];
#pragma unroll
    for (int g = 0; g < 4; g++) {
        int r = g * 16 + rowm;
        r8[g] = (uint32_t)r * 8;
        rx[g] = (uint32_t)(r & 7);
    }

    float oacc[2][8][4];
#pragma unroll
    for (int h = 0; h < 2; h++)
#pragma unroll
        for (int i = 0; i < 8; i++)
#pragma unroll
            for (int e = 0; e < 4; e++) oacc[h][i][e] = 0.f;
    float rsacc[2][4];
#pragma unroll
    for (int h = 0; h < 2; h++)
#pragma unroll
        for (int e = 0; e < 4; e++) rsacc[h][e] = 0.f;

#pragma unroll
    for (int t = 0; t < 8; t++) {
        const int s = t % 3;                     // compile-time after unroll
        CP_WAIT(1);
        __syncthreads();
        if (t + 2 < 8) {
            const int s2 = (t + 2) % 3;
            const uint32_t stb = sb + 16384 + s2 * 16384;
            const ptrdiff_t ko = (ptrdiff_t)(t + 2) * 8192;
#pragma unroll
            for (int i = 0; i < 4; i++) {
                CP16(stb + lso[i], Kg + ko + lgo[i]);
                CP16(stb + 8192 + lso[i], Vg + ko + lgo[i]);
            }
        }
        CP_COMMIT();

        const uint32_t Kst = sb + 16384 + s * 16384;
        const uint32_t Vst = Kst + 8192;

        uint32_t sacc[2][8][2];
#pragma unroll
        for (int h = 0; h < 2; h++)
#pragma unroll
            for (int nt = 0; nt < 8; nt++) {
                sacc[h][nt][0] = 0u;
                sacc[h][nt][1] = 0u;
            }
#pragma unroll
        for (int g = 0; g < 4; g++) {
#pragma unroll
            for (int ks = 0; ks < 4; ks++) {
                const uint32_t c = ks * 2 + ca;
                uint32_t r0, r1, r2, r3;
                ldsm4(r0, r1, r2, r3, Kst + (r8[g] + (c ^ rx[g])) * 16);
                mma16h(sacc[0][2 * g], aQ[0][ks], r0, r2);
                mma16h(sacc[0][2 * g + 1], aQ[0][ks], r1, r3);
                mma16h(sacc[1][2 * g], aQ[1][ks], r0, r2);
                mma16h(sacc[1][2 * g + 1], aQ[1][ks], r1, r3);
            }
        }

#pragma unroll
        for (int h = 0; h < 2; h++)
#pragma unroll
            for (int nt = 0; nt < 8; nt++) {
                sacc[h][nt][0] = ex2h2(sacc[h][nt][0]);
                sacc[h][nt][1] = ex2h2(sacc[h][nt][1]);
            }

#pragma unroll
        for (int jj = 0; jj < 4; jj++) {
            uint32_t aP0[4] = {sacc[0][2 * jj][0], sacc[0][2 * jj][1],
                               sacc[0][2 * jj + 1][0], sacc[0][2 * jj + 1][1]};
            uint32_t aP1[4] = {sacc[1][2 * jj][0], sacc[1][2 * jj][1],
                               sacc[1][2 * jj + 1][0], sacc[1][2 * jj + 1][1]};
#pragma unroll
            for (int g4 = 0; g4 < 4; g4++) {
                const uint32_t c = g4 * 2 + ca;
                uint32_t v0, v1, v2, v3;
                ldsm4t(v0, v1, v2, v3, Vst + (r8[jj] + (c ^ rx[jj])) * 16);
                mma16(oacc[0][2 * g4], aP0, v0, v1);
                mma16(oacc[0][2 * g4 + 1], aP0, v2, v3);
                mma16(oacc[1][2 * g4], aP1, v0, v1);
                mma16(oacc[1][2 * g4 + 1], aP1, v2, v3);
            }
            mma16(rsacc[0], aP0, ONES_H2, ONES_H2);
            mma16(rsacc[1], aP1, ONES_H2, ONES_H2);
        }
    }

#pragma unroll
    for (int h = 0; h < 2; h++) {
        const int qrow = q0 + w * 32 + h * 16 + (lane >> 2);
        __half* po0 = g_po + (((size_t)(z * BATCH * HEADS + bh)) * SEQ + qrow) * HD + 2 * qd;
        __half* po1 = po0 + (size_t)8 * HD;
#pragma unroll
        for (int od = 0; od < 8; od++) {
            *(__half2*)(po0 + od * 8) = __floats2half2_rn(oacc[h][od][0], oacc[h][od][1]);
            *(__half2*)(po1 + od * 8) = __floats2half2_rn(oacc[h][od][2], oacc[h][od][3]);
        }
        if (qd == 0) {
            float* pl = g_pl + ((size_t)(z * BATCH * HEADS + bh)) * SEQ + qrow;
            pl[0] = rsacc[h][0];
            pl[8] = rsacc[h][2];
        }
    }
}

// ---------------------------------------------------------------------------
// Merge + normalize.
// ---------------------------------------------------------------------------
__global__ void __launch_bounds__(256)
merge_h(float* __restrict__ out)
{
    const int idx = blockIdx.x * blockDim.x + threadIdx.x;
    const int dc = idx & 7;
    const int q = (idx >> 3) & (SEQ - 1);
    const int bh = idx >> 14;

    float acc[8];
#pragma unroll
    for (int i = 0; i < 8; i++) acc[i] = 0.f;
    float l = 0.f;

#pragma unroll
    for (int z = 0; z < NSPLIT; z++) {
        const size_t base = ((size_t)(z * BATCH * HEADS + bh)) * SEQ + q;
        uint4 u = *(const uint4*)(g_po + base * HD + dc * 8);
        float2 f;
        f = __half22float2(*(__half2*)&u.x); acc[0] += f.x; acc[1] += f.y;
        f = __half22float2(*(__half2*)&u.y); acc[2] += f.x; acc[3] += f.y;
        f = __half22float2(*(__half2*)&u.z); acc[4] += f.x; acc[5] += f.y;
        f = __half22float2(*(__half2*)&u.w); acc[6] += f.x; acc[7] += f.y;
        l += g_pl[base];
    }
    const float inv = 1.f / l;
    const int b = bh >> 4, h = bh & 15;
    float* o = out + ((size_t)(b * SEQ + q)) * EMB + h * 64 + dc * 8;
    float4 v;
    v.x = acc[0] * inv; v.y = acc[1] * inv; v.z = acc[2] * inv; v.w = acc[3] * inv;
    *(float4*)o = v;
    v.x = acc[4] * inv; v.y = acc[5] * inv; v.z = acc[6] * inv; v.w = acc[7] * inv;
    *(float4*)(o + 4) = v;
}

extern "C" void kernel_launch(void* const* d_in, const int* in_sizes, int n_in,
                              void* d_out, int out_size)
{
    const float* x = (const float*)d_in[0];
    const float* w = (const float*)d_in[1];
    const float* b = (const float*)d_in[2];
    float* out = (float*)d_out;

    __half* xh;  cudaGetSymbolAddress((void**)&xh, g_xh);
    __half* wh;  cudaGetSymbolAddress((void**)&wh, g_wh);

    cudaFuncSetAttribute(qkv_h, cudaFuncAttributeMaxDynamicSharedMemorySize, G_SMEM);
    cudaFuncSetAttribute(attn_h, cudaFuncAttributeMaxDynamicSharedMemorySize, A_SMEM);

    const int n4x = BATCH * SEQ * EMB / 4;
    const int n4w = 3 * EMB * EMB / 4;
    cvt_h<<<592, 256>>>(x, w, xh, wh, n4x, n4x + n4w);
    qkv_h<<<dim3(3 * EMB / 64, BATCH * SEQ / 128), 128, G_SMEM>>>(b);
    attn_h<<<dim3(SEQ / 128, BATCH * HEADS, NSPLIT), 128, A_SMEM>>>();
    merge_h<<<(BATCH * HEADS * SEQ * HD / 8) / 256, 256>>>(out);
}